// round 4
// baseline (speedup 1.0000x reference)
#include <cuda_runtime.h>
#include <cstdint>

#define B_ 8
#define L_ 2048
#define H_ 1024

// Scratch: __device__ globals (no cudaMalloc allowed anywhere)
__device__ float g_q[(size_t)B_ * L_ * H_];    // 64 MB
__device__ float g_k[(size_t)B_ * L_ * H_];    // 64 MB
__device__ float g_v[(size_t)B_ * L_ * H_];    // 64 MB
__device__ float g_s[(size_t)B_ * L_ * L_];    // 128 MB
__device__ float g_x[(size_t)B_ * L_ * H_];    // 64 MB  tf32-rounded x
__device__ float g_w[(size_t)3 * H_ * H_];     // 12 MB  tf32-rounded Wq|Wk|Wv

// ---------------- tf32 mma.sync GEMM, cp.async 4-stage pipeline ----------------
// Block tile 128x128, BK=16, 8 warps as 2(M) x 4(N), warp tile 64x32.
#define BMT 128
#define BNT 128
#define BKT 16
#define STAGES 4
#define SA 20     // K-major smem row stride (floats): conflict-free frags
#define SB 136    // N-major smem row stride (floats): conflict-free frags

#define NT_STAGE_B (BMT * SA * 4)            // 10240 bytes per operand stage
#define NT_SMEM    (2 * STAGES * NT_STAGE_B) // 81920
#define NN_BSTAGE_B (BKT * SB * 4)           // 8704
#define NN_SMEM    (STAGES * (NT_STAGE_B + NN_BSTAGE_B))

__device__ __forceinline__ unsigned f2tf(float f) {
    unsigned u;
    asm("cvt.rna.tf32.f32 %0, %1;" : "=r"(u) : "f"(f));
    return u;
}
__device__ __forceinline__ uint32_t smem_u32(const void* p) {
    uint32_t a;
    asm("{ .reg .u64 t; cvta.to.shared.u64 t, %1; cvt.u32.u64 %0, t; }" : "=r"(a) : "l"(p));
    return a;
}
__device__ __forceinline__ void cp16(uint32_t dst, const void* src) {
    asm volatile("cp.async.cg.shared.global [%0], [%1], 16;" :: "r"(dst), "l"(src));
}
#define CP_COMMIT() asm volatile("cp.async.commit_group;" ::: "memory")
#define CP_WAIT2()  asm volatile("cp.async.wait_group 2;" ::: "memory")

__device__ __forceinline__ void mma_tf32(float& d0, float& d1, float& d2, float& d3,
                                         unsigned a0, unsigned a1, unsigned a2, unsigned a3,
                                         unsigned b0, unsigned b1) {
    asm volatile(
        "mma.sync.aligned.m16n8k8.row.col.f32.tf32.tf32.f32 "
        "{%0,%1,%2,%3}, {%4,%5,%6,%7}, {%8,%9}, {%0,%1,%2,%3};\n"
        : "+f"(d0), "+f"(d1), "+f"(d2), "+f"(d3)
        : "r"(a0), "r"(a1), "r"(a2), "r"(a3), "r"(b0), "r"(b1));
}

// C[M,N] = scale*(A[M,K]*B[N,K]^T + bias); K-contiguous operands (NT).
// roundOut: round stores to tf32 (rna). maskDiag: diagonal -> -FLT_MAX.
__global__ __launch_bounds__(256, 2) void gemm_nt_cp(
    const float* __restrict__ A, const float* __restrict__ Bm,
    const float* __restrict__ bias, float* __restrict__ C,
    int M, int N, int K, float scale, int maskDiag, int roundOut,
    long long sA, long long sB, long long sC)
{
    extern __shared__ char sm[];
    const uint32_t smb = smem_u32(sm);

    A  += (long long)blockIdx.z * sA;
    Bm += (long long)blockIdx.z * sB;
    C  += (long long)blockIdx.z * sC;

    const int tid  = threadIdx.x;
    const int warp = tid >> 5;
    const int lane = tid & 31;
    const int lq = lane >> 2, lr = lane & 3;
    const int wm = warp >> 2, wn = warp & 3;
    const int rowBase = blockIdx.y * BMT;
    const int colBase = blockIdx.x * BNT;

    // staging mapping: 128 rows x 4 float4 (16 floats) per matrix; 2 cp/thread/matrix
    const int srow = tid >> 1;             // 0..127
    const int sq   = (tid & 1) * 2;        // 0 or 2 (float4 index; +1 = second)
    const float* Arow = A  + (long long)(rowBase + srow) * K;
    const float* Brow = Bm + (long long)(colBase + srow) * K;
    const uint32_t stsA = smb + srow * (SA * 4) + sq * 16;
    const uint32_t stsB = smb + STAGES * NT_STAGE_B + srow * (SA * 4) + sq * 16;

    auto stage = [&](int kc, int st) {
        const int koff = kc * BKT + sq * 4;
        const uint32_t so = st * NT_STAGE_B;
        cp16(stsA + so,      Arow + koff);
        cp16(stsA + so + 16, Arow + koff + 4);
        cp16(stsB + so,      Brow + koff);
        cp16(stsB + so + 16, Brow + koff + 4);
    };

    float acc[4][4][4];
#pragma unroll
    for (int i = 0; i < 4; i++)
#pragma unroll
        for (int j = 0; j < 4; j++)
#pragma unroll
            for (int r = 0; r < 4; r++) acc[i][j][r] = 0.0f;

    const int NC = K / BKT;
#pragma unroll
    for (int st = 0; st < STAGES - 1; st++) { stage(st, st); CP_COMMIT(); }

    const unsigned* aSm = (const unsigned*)sm;
    const unsigned* bSm = (const unsigned*)(sm + STAGES * NT_STAGE_B);

    for (int c = 0; c < NC; c++) {
        CP_WAIT2();
        __syncthreads();
        if (c + STAGES - 1 < NC) stage(c + STAGES - 1, (c + STAGES - 1) & (STAGES - 1));
        CP_COMMIT();

        const unsigned* aS = aSm + (c & (STAGES - 1)) * (NT_STAGE_B / 4);
        const unsigned* bS = bSm + (c & (STAGES - 1)) * (NT_STAGE_B / 4);
#pragma unroll
        for (int ks = 0; ks < 2; ks++) {
            unsigned af[4][4], bf[4][2];
#pragma unroll
            for (int mt = 0; mt < 4; mt++) {
                const int base = (wm * 64 + mt * 16 + lq) * SA + ks * 8 + lr;
                af[mt][0] = aS[base];
                af[mt][1] = aS[base + 8 * SA];
                af[mt][2] = aS[base + 4];
                af[mt][3] = aS[base + 8 * SA + 4];
            }
#pragma unroll
            for (int nt = 0; nt < 4; nt++) {
                const int base = (wn * 32 + nt * 8 + lq) * SA + ks * 8 + lr;
                bf[nt][0] = bS[base];
                bf[nt][1] = bS[base + 4];
            }
#pragma unroll
            for (int mt = 0; mt < 4; mt++)
#pragma unroll
                for (int nt = 0; nt < 4; nt++)
                    mma_tf32(acc[mt][nt][0], acc[mt][nt][1], acc[mt][nt][2], acc[mt][nt][3],
                             af[mt][0], af[mt][1], af[mt][2], af[mt][3],
                             bf[nt][0], bf[nt][1]);
        }
    }

#pragma unroll
    for (int mt = 0; mt < 4; mt++) {
        const int row = rowBase + wm * 64 + mt * 16 + lq;
#pragma unroll
        for (int nt = 0; nt < 4; nt++) {
            const int col = colBase + wn * 32 + nt * 8 + 2 * lr;
            float v0 = acc[mt][nt][0], v1 = acc[mt][nt][1];
            float v2 = acc[mt][nt][2], v3 = acc[mt][nt][3];
            if (bias) { v0 += bias[col]; v1 += bias[col + 1]; v2 += bias[col]; v3 += bias[col + 1]; }
            v0 *= scale; v1 *= scale; v2 *= scale; v3 *= scale;
            if (roundOut) {
                v0 = __uint_as_float(f2tf(v0)); v1 = __uint_as_float(f2tf(v1));
                v2 = __uint_as_float(f2tf(v2)); v3 = __uint_as_float(f2tf(v3));
            }
            if (maskDiag) {
                if (row == col)     v0 = -3.402823466e38f;
                if (row == col + 1) v1 = -3.402823466e38f;
                if (row + 8 == col)     v2 = -3.402823466e38f;
                if (row + 8 == col + 1) v3 = -3.402823466e38f;
            }
            *(float2*)&C[(long long)row * N + col]       = make_float2(v0, v1);
            *(float2*)&C[(long long)(row + 8) * N + col] = make_float2(v2, v3);
        }
    }
}

// C[M,N] = A[M,K]*B[K,N]; B N-contiguous (NN). Batched via blockIdx.z.
__global__ __launch_bounds__(256, 2) void gemm_nn_cp(
    const float* __restrict__ A, const float* __restrict__ Bm,
    float* __restrict__ C, int M, int N, int K,
    long long sA, long long sB, long long sC)
{
    extern __shared__ char sm[];
    const uint32_t smb = smem_u32(sm);

    A  += (long long)blockIdx.z * sA;
    Bm += (long long)blockIdx.z * sB;
    C  += (long long)blockIdx.z * sC;

    const int tid  = threadIdx.x;
    const int warp = tid >> 5;
    const int lane = tid & 31;
    const int lq = lane >> 2, lr = lane & 3;
    const int wm = warp >> 2, wn = warp & 3;
    const int rowBase = blockIdx.y * BMT;
    const int colBase = blockIdx.x * BNT;

    // A staging: 128 rows x 16k ; 2 cp/thread
    const int srow = tid >> 1;
    const int sq   = (tid & 1) * 2;
    const float* Arow = A + (long long)(rowBase + srow) * K;
    const uint32_t stsA = smb + srow * (SA * 4) + sq * 16;
    // B staging: 16 k-rows x 128 n ; 2 cp/thread
    const int bkr = tid >> 4;              // 0..15
    const int bn4 = (tid & 15) * 2;        // float4 idx 0..30 step 2
    const float* Brow = Bm + colBase + bn4 * 4;
    const uint32_t stsB = smb + STAGES * NT_STAGE_B + bkr * (SB * 4) + bn4 * 16;

    auto stage = [&](int kc, int st) {
        const int koff = kc * BKT;
        cp16(stsA + st * NT_STAGE_B,       Arow + koff + sq * 4);
        cp16(stsA + st * NT_STAGE_B + 16,  Arow + koff + sq * 4 + 4);
        const float* bp = Brow + (long long)(koff + bkr) * N;
        cp16(stsB + st * NN_BSTAGE_B,      bp);
        cp16(stsB + st * NN_BSTAGE_B + 16, bp + 4);
    };

    float acc[4][4][4];
#pragma unroll
    for (int i = 0; i < 4; i++)
#pragma unroll
        for (int j = 0; j < 4; j++)
#pragma unroll
            for (int r = 0; r < 4; r++) acc[i][j][r] = 0.0f;

    const int NC = K / BKT;
#pragma unroll
    for (int st = 0; st < STAGES - 1; st++) { stage(st, st); CP_COMMIT(); }

    const unsigned* aSm = (const unsigned*)sm;
    const unsigned* bSm = (const unsigned*)(sm + STAGES * NT_STAGE_B);

    for (int c = 0; c < NC; c++) {
        CP_WAIT2();
        __syncthreads();
        if (c + STAGES - 1 < NC) stage(c + STAGES - 1, (c + STAGES - 1) & (STAGES - 1));
        CP_COMMIT();

        const unsigned* aS = aSm + (c & (STAGES - 1)) * (NT_STAGE_B / 4);
        const unsigned* bS = bSm + (c & (STAGES - 1)) * (NN_BSTAGE_B / 4);
#pragma unroll
        for (int ks = 0; ks < 2; ks++) {
            unsigned af[4][4], bf[4][2];
#pragma unroll
            for (int mt = 0; mt < 4; mt++) {
                const int base = (wm * 64 + mt * 16 + lq) * SA + ks * 8 + lr;
                af[mt][0] = aS[base];
                af[mt][1] = aS[base + 8 * SA];
                af[mt][2] = aS[base + 4];
                af[mt][3] = aS[base + 8 * SA + 4];
            }
#pragma unroll
            for (int nt = 0; nt < 4; nt++) {
                const int col = wn * 32 + nt * 8 + lq;
                bf[nt][0] = bS[(ks * 8 + lr) * SB + col];
                bf[nt][1] = bS[(ks * 8 + lr + 4) * SB + col];
            }
#pragma unroll
            for (int mt = 0; mt < 4; mt++)
#pragma unroll
                for (int nt = 0; nt < 4; nt++)
                    mma_tf32(acc[mt][nt][0], acc[mt][nt][1], acc[mt][nt][2], acc[mt][nt][3],
                             af[mt][0], af[mt][1], af[mt][2], af[mt][3],
                             bf[nt][0], bf[nt][1]);
        }
    }

#pragma unroll
    for (int mt = 0; mt < 4; mt++) {
        const int row = rowBase + wm * 64 + mt * 16 + lq;
#pragma unroll
        for (int nt = 0; nt < 4; nt++) {
            const int col = colBase + wn * 32 + nt * 8 + 2 * lr;
            *(float2*)&C[(long long)row * N + col] =
                make_float2(acc[mt][nt][0], acc[mt][nt][1]);
            *(float2*)&C[(long long)(row + 8) * N + col] =
                make_float2(acc[mt][nt][2], acc[mt][nt][3]);
        }
    }
}

// Round an f32 array to tf32 (rna), in -> out. Grid-stride float4.
__global__ __launch_bounds__(256) void round_tf32(const float* __restrict__ in,
                                                  float* __restrict__ out, long long n4)
{
    const long long i0 = (long long)blockIdx.x * blockDim.x + threadIdx.x;
    const long long stride = (long long)gridDim.x * blockDim.x;
    for (long long i = i0; i < n4; i += stride) {
        float4 v = ((const float4*)in)[i];
        ((float4*)out)[i] = make_float4(
            __uint_as_float(f2tf(v.x)), __uint_as_float(f2tf(v.y)),
            __uint_as_float(f2tf(v.z)), __uint_as_float(f2tf(v.w)));
    }
}

// In-place row softmax over 2048 columns; output rounded to tf32.
__global__ __launch_bounds__(256) void softmax_rows(float* __restrict__ S)
{
    __shared__ float red[256];
    float* row = S + (long long)blockIdx.x * L_;
    const int tid = threadIdx.x;

    float vals[8];
    float lmax = -3.402823466e38f;
#pragma unroll
    for (int i = 0; i < 8; i++) {
        vals[i] = row[tid + i * 256];
        lmax = fmaxf(lmax, vals[i]);
    }
    red[tid] = lmax;
    __syncthreads();
    for (int s = 128; s > 0; s >>= 1) {
        if (tid < s) red[tid] = fmaxf(red[tid], red[tid + s]);
        __syncthreads();
    }
    const float m = red[0];
    __syncthreads();

    float lsum = 0.0f;
#pragma unroll
    for (int i = 0; i < 8; i++) {
        vals[i] = __expf(vals[i] - m);
        lsum += vals[i];
    }
    red[tid] = lsum;
    __syncthreads();
    for (int s = 128; s > 0; s >>= 1) {
        if (tid < s) red[tid] += red[tid + s];
        __syncthreads();
    }
    const float inv = 1.0f / red[0];
#pragma unroll
    for (int i = 0; i < 8; i++)
        row[tid + i * 256] = __uint_as_float(f2tf(vals[i] * inv));
}

extern "C" void kernel_launch(void* const* d_in, const int* in_sizes, int n_in,
                              void* d_out, int out_size)
{
    const float* x  = (const float*)d_in[0];
    const float* Wq = (const float*)d_in[1];
    const float* bq = (const float*)d_in[2];
    const float* Wk = (const float*)d_in[3];
    const float* bk = (const float*)d_in[4];
    const float* Wv = (const float*)d_in[5];
    const float* bv = (const float*)d_in[6];
    float* out = (float*)d_out;

    float *q, *k, *v, *s, *xr, *wr;
    cudaGetSymbolAddress((void**)&q,  g_q);
    cudaGetSymbolAddress((void**)&k,  g_k);
    cudaGetSymbolAddress((void**)&v,  g_v);
    cudaGetSymbolAddress((void**)&s,  g_s);
    cudaGetSymbolAddress((void**)&xr, g_x);
    cudaGetSymbolAddress((void**)&wr, g_w);

    cudaFuncSetAttribute(gemm_nt_cp, cudaFuncAttributeMaxDynamicSharedMemorySize, NT_SMEM);
    cudaFuncSetAttribute(gemm_nn_cp, cudaFuncAttributeMaxDynamicSharedMemorySize, NN_SMEM);

    const dim3 blk(256);
    const long long sQK = (long long)L_ * H_;
    const long long sSS = (long long)L_ * L_;

    // Pre-round x and W to tf32 so cp.async-staged mma inputs are exact.
    round_tf32<<<1024, blk>>>(x, xr, (long long)B_ * L_ * H_ / 4);
    round_tf32<<<256, blk>>>(Wq, wr,               (long long)H_ * H_ / 4);
    round_tf32<<<256, blk>>>(Wk, wr + (size_t)H_ * H_,     (long long)H_ * H_ / 4);
    round_tf32<<<256, blk>>>(Wv, wr + (size_t)2 * H_ * H_, (long long)H_ * H_ / 4);

    // QKV projections (q folded with 1/H scale); outputs rounded to tf32
    dim3 gQKV(H_ / BNT, (B_ * L_) / BMT, 1);
    gemm_nt_cp<<<gQKV, blk, NT_SMEM>>>(xr, wr,                     bq, q, B_ * L_, H_, H_, 1.0f / (float)H_, 0, 1, 0, 0, 0);
    gemm_nt_cp<<<gQKV, blk, NT_SMEM>>>(xr, wr + (size_t)H_ * H_,   bk, k, B_ * L_, H_, H_, 1.0f, 0, 1, 0, 0, 0);
    gemm_nt_cp<<<gQKV, blk, NT_SMEM>>>(xr, wr + (size_t)2*H_*H_,   bv, v, B_ * L_, H_, H_, 1.0f, 0, 1, 0, 0, 0);

    // Scores: S[b] = q[b]*k[b]^T, diagonal masked (kept f32; softmax rounds)
    dim3 gS(L_ / BNT, L_ / BMT, B_);
    gemm_nt_cp<<<gS, blk, NT_SMEM>>>(q, k, nullptr, s, L_, L_, H_, 1.0f, 1, 0, sQK, sQK, sSS);

    softmax_rows<<<B_ * L_, blk>>>(s);

    // Output: out[b] = S[b]*v[b]
    dim3 gO(H_ / BNT, L_ / BMT, B_);
    gemm_nn_cp<<<gO, blk, NN_SMEM>>>(s, v, out, L_, H_, L_, sSS, sQK, sQK);
}

// round 5
// speedup vs baseline: 1.1837x; 1.1837x over previous
#include <cuda_runtime.h>
#include <cstdint>

#define B_ 8
#define L_ 2048
#define H_ 1024

// Scratch: __device__ globals (no cudaMalloc allowed anywhere)
__device__ float g_q[(size_t)B_ * L_ * H_];    // 64 MB
__device__ float g_k[(size_t)B_ * L_ * H_];    // 64 MB
__device__ float g_v[(size_t)B_ * L_ * H_];    // 64 MB
__device__ float g_s[(size_t)B_ * L_ * L_];    // 128 MB
__device__ float g_x[(size_t)B_ * L_ * H_];    // 64 MB  tf32-rounded x
__device__ float g_w[(size_t)3 * H_ * H_];     // 12 MB  tf32-rounded Wq|Wk|Wv

// ---- tf32 mma.sync GEMM: block 128x128, 4 warps (2x2) of 64x64, BK=16, 3-stage cp.async
#define BMT 128
#define BNT 128
#define BKT 16
#define STAGES 3
#define SA 20     // K-major smem row stride (floats): conflict-free frags
#define SB 136    // N-major smem row stride (floats): conflict-free frags

#define A_STAGE_B (BMT * SA * 4)                 // 10240 bytes
#define BT_STAGE_B (BNT * SA * 4)                // 10240 (NT: B K-major)
#define BN_STAGE_B (BKT * SB * 4)                // 8704  (NN: B N-major)
#define NT_SMEM (STAGES * (A_STAGE_B + BT_STAGE_B))   // 61440
#define NN_SMEM (STAGES * (A_STAGE_B + BN_STAGE_B))   // 56832

__device__ __forceinline__ unsigned f2tf(float f) {
    unsigned u;
    asm("cvt.rna.tf32.f32 %0, %1;" : "=r"(u) : "f"(f));
    return u;
}
__device__ __forceinline__ uint32_t smem_u32(const void* p) {
    uint32_t a;
    asm("{ .reg .u64 t; cvta.to.shared.u64 t, %1; cvt.u32.u64 %0, t; }" : "=r"(a) : "l"(p));
    return a;
}
__device__ __forceinline__ void cp16(uint32_t dst, const void* src) {
    asm volatile("cp.async.cg.shared.global [%0], [%1], 16;" :: "r"(dst), "l"(src));
}
#define CP_COMMIT() asm volatile("cp.async.commit_group;" ::: "memory")
#define CP_WAIT1()  asm volatile("cp.async.wait_group 1;" ::: "memory")

__device__ __forceinline__ void mma_tf32(float& d0, float& d1, float& d2, float& d3,
                                         unsigned a0, unsigned a1, unsigned a2, unsigned a3,
                                         unsigned b0, unsigned b1) {
    asm volatile(
        "mma.sync.aligned.m16n8k8.row.col.f32.tf32.tf32.f32 "
        "{%0,%1,%2,%3}, {%4,%5,%6,%7}, {%8,%9}, {%0,%1,%2,%3};\n"
        : "+f"(d0), "+f"(d1), "+f"(d2), "+f"(d3)
        : "r"(a0), "r"(a1), "r"(a2), "r"(a3), "r"(b0), "r"(b1));
}

// C[M,N] = scale*(A[M,K]*B[N,K]^T + bias); K-contiguous operands (NT).
__global__ __launch_bounds__(128, 2) void gemm_nt_cp(
    const float* __restrict__ A, const float* __restrict__ Bm,
    const float* __restrict__ bias, float* __restrict__ C,
    int M, int N, int K, float scale, int maskDiag, int roundOut,
    long long sA, long long sB, long long sC)
{
    extern __shared__ char sm[];
    const uint32_t smb = smem_u32(sm);

    A  += (long long)blockIdx.z * sA;
    Bm += (long long)blockIdx.z * sB;
    C  += (long long)blockIdx.z * sC;

    const int tid  = threadIdx.x;
    const int warp = tid >> 5;
    const int lane = tid & 31;
    const int lq = lane >> 2, lr = lane & 3;
    const int wm = warp >> 1, wn = warp & 1;        // 2x2 warps, 64x64 each
    const int rowBase = blockIdx.y * BMT;
    const int colBase = blockIdx.x * BNT;

    const uint32_t aBase = smb;
    const uint32_t bBase = smb + STAGES * A_STAGE_B;

    // stage: 512 float4 per matrix / 128 threads = 4 cp16 each
    auto stage = [&](int kc, int st) {
        const int koff = kc * BKT;
        const uint32_t aso = aBase + st * A_STAGE_B;
        const uint32_t bso = bBase + st * BT_STAGE_B;
#pragma unroll
        for (int i = 0; i < 4; i++) {
            const int f = i * 128 + tid;
            const int row = f >> 2, k4 = f & 3;
            cp16(aso + row * (SA * 4) + k4 * 16, A  + (long long)(rowBase + row) * K + koff + k4 * 4);
            cp16(bso + row * (SA * 4) + k4 * 16, Bm + (long long)(colBase + row) * K + koff + k4 * 4);
        }
    };

    float acc[4][8][4];
#pragma unroll
    for (int i = 0; i < 4; i++)
#pragma unroll
        for (int j = 0; j < 8; j++)
#pragma unroll
            for (int r = 0; r < 4; r++) acc[i][j][r] = 0.0f;

    const int NC = K / BKT;
    stage(0, 0); CP_COMMIT();
    stage(1, 1); CP_COMMIT();

    const unsigned* aSm = (const unsigned*)sm;
    const unsigned* bSm = (const unsigned*)(sm + STAGES * A_STAGE_B);

    int bufC = 0, bufS = 2;
    for (int c = 0; c < NC; c++) {
        CP_WAIT1();
        __syncthreads();
        if (c + 2 < NC) stage(c + 2, bufS);
        CP_COMMIT();

        const unsigned* aS = aSm + bufC * (A_STAGE_B / 4);
        const unsigned* bS = bSm + bufC * (BT_STAGE_B / 4);
#pragma unroll
        for (int ks = 0; ks < 2; ks++) {
            unsigned af[4][4], bf[8][2];
#pragma unroll
            for (int mt = 0; mt < 4; mt++) {
                const int base = (wm * 64 + mt * 16 + lq) * SA + ks * 8 + lr;
                af[mt][0] = aS[base];
                af[mt][1] = aS[base + 8 * SA];
                af[mt][2] = aS[base + 4];
                af[mt][3] = aS[base + 8 * SA + 4];
            }
#pragma unroll
            for (int nt = 0; nt < 8; nt++) {
                const int base = (wn * 64 + nt * 8 + lq) * SA + ks * 8 + lr;
                bf[nt][0] = bS[base];
                bf[nt][1] = bS[base + 4];
            }
#pragma unroll
            for (int mt = 0; mt < 4; mt++)
#pragma unroll
                for (int nt = 0; nt < 8; nt++)
                    mma_tf32(acc[mt][nt][0], acc[mt][nt][1], acc[mt][nt][2], acc[mt][nt][3],
                             af[mt][0], af[mt][1], af[mt][2], af[mt][3],
                             bf[nt][0], bf[nt][1]);
        }
        bufC = (bufC == STAGES - 1) ? 0 : bufC + 1;
        bufS = (bufS == STAGES - 1) ? 0 : bufS + 1;
    }

#pragma unroll
    for (int mt = 0; mt < 4; mt++) {
        const int row = rowBase + wm * 64 + mt * 16 + lq;
#pragma unroll
        for (int nt = 0; nt < 8; nt++) {
            const int col = colBase + wn * 64 + nt * 8 + 2 * lr;
            float v0 = acc[mt][nt][0], v1 = acc[mt][nt][1];
            float v2 = acc[mt][nt][2], v3 = acc[mt][nt][3];
            if (bias) { v0 += bias[col]; v1 += bias[col + 1]; v2 += bias[col]; v3 += bias[col + 1]; }
            v0 *= scale; v1 *= scale; v2 *= scale; v3 *= scale;
            if (roundOut) {
                v0 = __uint_as_float(f2tf(v0)); v1 = __uint_as_float(f2tf(v1));
                v2 = __uint_as_float(f2tf(v2)); v3 = __uint_as_float(f2tf(v3));
            }
            if (maskDiag) {
                if (row == col)     v0 = -3.402823466e38f;
                if (row == col + 1) v1 = -3.402823466e38f;
                if (row + 8 == col)     v2 = -3.402823466e38f;
                if (row + 8 == col + 1) v3 = -3.402823466e38f;
            }
            *(float2*)&C[(long long)row * N + col]       = make_float2(v0, v1);
            *(float2*)&C[(long long)(row + 8) * N + col] = make_float2(v2, v3);
        }
    }
}

// C[M,N] = A[M,K]*B[K,N]; B N-contiguous (NN). Batched via blockIdx.z.
__global__ __launch_bounds__(128, 2) void gemm_nn_cp(
    const float* __restrict__ A, const float* __restrict__ Bm,
    float* __restrict__ C, int M, int N, int K,
    long long sA, long long sB, long long sC)
{
    extern __shared__ char sm[];
    const uint32_t smb = smem_u32(sm);

    A  += (long long)blockIdx.z * sA;
    Bm += (long long)blockIdx.z * sB;
    C  += (long long)blockIdx.z * sC;

    const int tid  = threadIdx.x;
    const int warp = tid >> 5;
    const int lane = tid & 31;
    const int lq = lane >> 2, lr = lane & 3;
    const int wm = warp >> 1, wn = warp & 1;
    const int rowBase = blockIdx.y * BMT;
    const int colBase = blockIdx.x * BNT;

    const uint32_t aBase = smb;
    const uint32_t bBase = smb + STAGES * A_STAGE_B;

    auto stage = [&](int kc, int st) {
        const int koff = kc * BKT;
        const uint32_t aso = aBase + st * A_STAGE_B;
        const uint32_t bso = bBase + st * BN_STAGE_B;
#pragma unroll
        for (int i = 0; i < 4; i++) {
            const int f = i * 128 + tid;
            const int arow = f >> 2, ak4 = f & 3;
            cp16(aso + arow * (SA * 4) + ak4 * 16, A + (long long)(rowBase + arow) * K + koff + ak4 * 4);
            const int brow = f >> 5, bc4 = f & 31;   // 16 rows x 32 float4
            cp16(bso + brow * (SB * 4) + bc4 * 16, Bm + (long long)(koff + brow) * N + colBase + bc4 * 4);
        }
    };

    float acc[4][8][4];
#pragma unroll
    for (int i = 0; i < 4; i++)
#pragma unroll
        for (int j = 0; j < 8; j++)
#pragma unroll
            for (int r = 0; r < 4; r++) acc[i][j][r] = 0.0f;

    const int NC = K / BKT;
    stage(0, 0); CP_COMMIT();
    stage(1, 1); CP_COMMIT();

    const unsigned* aSm = (const unsigned*)sm;
    const unsigned* bSm = (const unsigned*)(sm + STAGES * A_STAGE_B);

    int bufC = 0, bufS = 2;
    for (int c = 0; c < NC; c++) {
        CP_WAIT1();
        __syncthreads();
        if (c + 2 < NC) stage(c + 2, bufS);
        CP_COMMIT();

        const unsigned* aS = aSm + bufC * (A_STAGE_B / 4);
        const unsigned* bS = bSm + bufC * (BN_STAGE_B / 4);
#pragma unroll
        for (int ks = 0; ks < 2; ks++) {
            unsigned af[4][4], bf[8][2];
#pragma unroll
            for (int mt = 0; mt < 4; mt++) {
                const int base = (wm * 64 + mt * 16 + lq) * SA + ks * 8 + lr;
                af[mt][0] = aS[base];
                af[mt][1] = aS[base + 8 * SA];
                af[mt][2] = aS[base + 4];
                af[mt][3] = aS[base + 8 * SA + 4];
            }
#pragma unroll
            for (int nt = 0; nt < 8; nt++) {
                const int col = wn * 64 + nt * 8 + lq;
                bf[nt][0] = bS[(ks * 8 + lr) * SB + col];
                bf[nt][1] = bS[(ks * 8 + lr + 4) * SB + col];
            }
#pragma unroll
            for (int mt = 0; mt < 4; mt++)
#pragma unroll
                for (int nt = 0; nt < 8; nt++)
                    mma_tf32(acc[mt][nt][0], acc[mt][nt][1], acc[mt][nt][2], acc[mt][nt][3],
                             af[mt][0], af[mt][1], af[mt][2], af[mt][3],
                             bf[nt][0], bf[nt][1]);
        }
        bufC = (bufC == STAGES - 1) ? 0 : bufC + 1;
        bufS = (bufS == STAGES - 1) ? 0 : bufS + 1;
    }

#pragma unroll
    for (int mt = 0; mt < 4; mt++) {
        const int row = rowBase + wm * 64 + mt * 16 + lq;
#pragma unroll
        for (int nt = 0; nt < 8; nt++) {
            const int col = colBase + wn * 64 + nt * 8 + 2 * lr;
            *(float2*)&C[(long long)row * N + col] =
                make_float2(acc[mt][nt][0], acc[mt][nt][1]);
            *(float2*)&C[(long long)(row + 8) * N + col] =
                make_float2(acc[mt][nt][2], acc[mt][nt][3]);
        }
    }
}

// Round an f32 array to tf32 (rna), in -> out. Grid-stride float4.
__global__ __launch_bounds__(256) void round_tf32(const float* __restrict__ in,
                                                  float* __restrict__ out, long long n4)
{
    const long long i0 = (long long)blockIdx.x * blockDim.x + threadIdx.x;
    const long long stride = (long long)gridDim.x * blockDim.x;
    for (long long i = i0; i < n4; i += stride) {
        float4 v = ((const float4*)in)[i];
        ((float4*)out)[i] = make_float4(
            __uint_as_float(f2tf(v.x)), __uint_as_float(f2tf(v.y)),
            __uint_as_float(f2tf(v.z)), __uint_as_float(f2tf(v.w)));
    }
}

// In-place row softmax over 2048 columns; output rounded to tf32.
__global__ __launch_bounds__(256) void softmax_rows(float* __restrict__ S)
{
    __shared__ float red[256];
    float* row = S + (long long)blockIdx.x * L_;
    const int tid = threadIdx.x;

    float vals[8];
    float lmax = -3.402823466e38f;
#pragma unroll
    for (int i = 0; i < 8; i++) {
        vals[i] = row[tid + i * 256];
        lmax = fmaxf(lmax, vals[i]);
    }
    red[tid] = lmax;
    __syncthreads();
    for (int s = 128; s > 0; s >>= 1) {
        if (tid < s) red[tid] = fmaxf(red[tid], red[tid + s]);
        __syncthreads();
    }
    const float m = red[0];
    __syncthreads();

    float lsum = 0.0f;
#pragma unroll
    for (int i = 0; i < 8; i++) {
        vals[i] = __expf(vals[i] - m);
        lsum += vals[i];
    }
    red[tid] = lsum;
    __syncthreads();
    for (int s = 128; s > 0; s >>= 1) {
        if (tid < s) red[tid] += red[tid + s];
        __syncthreads();
    }
    const float inv = 1.0f / red[0];
#pragma unroll
    for (int i = 0; i < 8; i++)
        row[tid + i * 256] = __uint_as_float(f2tf(vals[i] * inv));
}

extern "C" void kernel_launch(void* const* d_in, const int* in_sizes, int n_in,
                              void* d_out, int out_size)
{
    const float* x  = (const float*)d_in[0];
    const float* Wq = (const float*)d_in[1];
    const float* bq = (const float*)d_in[2];
    const float* Wk = (const float*)d_in[3];
    const float* bk = (const float*)d_in[4];
    const float* Wv = (const float*)d_in[5];
    const float* bv = (const float*)d_in[6];
    float* out = (float*)d_out;

    float *q, *k, *v, *s, *xr, *wr;
    cudaGetSymbolAddress((void**)&q,  g_q);
    cudaGetSymbolAddress((void**)&k,  g_k);
    cudaGetSymbolAddress((void**)&v,  g_v);
    cudaGetSymbolAddress((void**)&s,  g_s);
    cudaGetSymbolAddress((void**)&xr, g_x);
    cudaGetSymbolAddress((void**)&wr, g_w);

    cudaFuncSetAttribute(gemm_nt_cp, cudaFuncAttributeMaxDynamicSharedMemorySize, NT_SMEM);
    cudaFuncSetAttribute(gemm_nn_cp, cudaFuncAttributeMaxDynamicSharedMemorySize, NN_SMEM);

    const long long sQK = (long long)L_ * H_;
    const long long sSS = (long long)L_ * L_;

    // Pre-round x and W to tf32 so cp.async-staged mma inputs are exact.
    round_tf32<<<1024, 256>>>(x, xr, (long long)B_ * L_ * H_ / 4);
    round_tf32<<<256, 256>>>(Wq, wr,                   (long long)H_ * H_ / 4);
    round_tf32<<<256, 256>>>(Wk, wr + (size_t)H_ * H_,     (long long)H_ * H_ / 4);
    round_tf32<<<256, 256>>>(Wv, wr + (size_t)2 * H_ * H_, (long long)H_ * H_ / 4);

    const dim3 blk(128);

    // QKV projections (q folded with 1/H scale); outputs rounded to tf32
    dim3 gQKV(H_ / BNT, (B_ * L_) / BMT, 1);
    gemm_nt_cp<<<gQKV, blk, NT_SMEM>>>(xr, wr,                   bq, q, B_ * L_, H_, H_, 1.0f / (float)H_, 0, 1, 0, 0, 0);
    gemm_nt_cp<<<gQKV, blk, NT_SMEM>>>(xr, wr + (size_t)H_ * H_, bk, k, B_ * L_, H_, H_, 1.0f, 0, 1, 0, 0, 0);
    gemm_nt_cp<<<gQKV, blk, NT_SMEM>>>(xr, wr + (size_t)2*H_*H_, bv, v, B_ * L_, H_, H_, 1.0f, 0, 1, 0, 0, 0);

    // Scores: S[b] = q[b]*k[b]^T, diagonal masked (kept f32; softmax rounds)
    dim3 gS(L_ / BNT, L_ / BMT, B_);
    gemm_nt_cp<<<gS, blk, NT_SMEM>>>(q, k, nullptr, s, L_, L_, H_, 1.0f, 1, 0, sQK, sQK, sSS);

    softmax_rows<<<B_ * L_, 256>>>(s);

    // Output: out[b] = S[b]*v[b]
    dim3 gO(H_ / BNT, L_ / BMT, B_);
    gemm_nn_cp<<<gO, blk, NN_SMEM>>>(s, v, out, L_, H_, L_, sSS, sQK, sQK);
}

// round 6
// speedup vs baseline: 1.2638x; 1.0676x over previous
#include <cuda_runtime.h>
#include <cstdint>

#define B_ 8
#define L_ 2048
#define H_ 1024

// Scratch: __device__ globals (no cudaMalloc allowed anywhere)
__device__ float g_q[(size_t)B_ * L_ * H_];    // 64 MB
__device__ float g_k[(size_t)B_ * L_ * H_];    // 64 MB
__device__ float g_v[(size_t)B_ * L_ * H_];    // 64 MB
__device__ float g_s[(size_t)B_ * L_ * L_];    // 128 MB
__device__ float g_x[(size_t)B_ * L_ * H_];    // 64 MB  tf32-rounded x, then V^T
__device__ float g_w[(size_t)3 * H_ * H_];     // 12 MB  tf32-rounded Wq|Wk|Wv

// ---- tf32 mma.sync GEMM: block 128x128, 4 warps (2x2) of 64x64, BK=16,
// ---- 3-stage cp.async, ldmatrix.x4 fragment loads.
#define BMT 128
#define BNT 128
#define BKT 16
#define STAGES 3
#define SA 20     // K-major smem row stride (floats): conflict-free ldmatrix

#define A_STAGE_B (BMT * SA * 4)                 // 10240 bytes
#define BT_STAGE_B (BNT * SA * 4)                // 10240
#define NT_SMEM (STAGES * (A_STAGE_B + BT_STAGE_B))   // 61440

__device__ __forceinline__ unsigned f2tf(float f) {
    unsigned u;
    asm("cvt.rna.tf32.f32 %0, %1;" : "=r"(u) : "f"(f));
    return u;
}
__device__ __forceinline__ uint32_t smem_u32(const void* p) {
    uint32_t a;
    asm("{ .reg .u64 t; cvta.to.shared.u64 t, %1; cvt.u32.u64 %0, t; }" : "=r"(a) : "l"(p));
    return a;
}
__device__ __forceinline__ void cp16(uint32_t dst, const void* src) {
    asm volatile("cp.async.cg.shared.global [%0], [%1], 16;" :: "r"(dst), "l"(src));
}
#define CP_COMMIT() asm volatile("cp.async.commit_group;" ::: "memory")
#define CP_WAIT1()  asm volatile("cp.async.wait_group 1;" ::: "memory")

#define LDSM_X4(d0, d1, d2, d3, addr)                                        \
    asm volatile("ldmatrix.sync.aligned.m8n8.x4.shared.b16 {%0,%1,%2,%3}, [%4];" \
        : "=r"(d0), "=r"(d1), "=r"(d2), "=r"(d3) : "r"(addr))

__device__ __forceinline__ void mma_tf32(float& d0, float& d1, float& d2, float& d3,
                                         unsigned a0, unsigned a1, unsigned a2, unsigned a3,
                                         unsigned b0, unsigned b1) {
    asm volatile(
        "mma.sync.aligned.m16n8k8.row.col.f32.tf32.tf32.f32 "
        "{%0,%1,%2,%3}, {%4,%5,%6,%7}, {%8,%9}, {%0,%1,%2,%3};\n"
        : "+f"(d0), "+f"(d1), "+f"(d2), "+f"(d3)
        : "r"(a0), "r"(a1), "r"(a2), "r"(a3), "r"(b0), "r"(b1));
}

// C[M,N] = scale*(A[M,K]*B[N,K]^T + bias); K-contiguous operands (NT).
__global__ __launch_bounds__(128, 2) void gemm_nt_cp(
    const float* __restrict__ A, const float* __restrict__ Bm,
    const float* __restrict__ bias, float* __restrict__ C,
    int M, int N, int K, float scale, int maskDiag, int roundOut,
    long long sA, long long sB, long long sC)
{
    extern __shared__ char sm[];
    const uint32_t smb = smem_u32(sm);

    A  += (long long)blockIdx.z * sA;
    Bm += (long long)blockIdx.z * sB;
    C  += (long long)blockIdx.z * sC;

    const int tid  = threadIdx.x;
    const int warp = tid >> 5;
    const int lane = tid & 31;
    const int lq = lane >> 2, lr = lane & 3;
    const int wm = warp >> 1, wn = warp & 1;        // 2x2 warps, 64x64 each
    const int rowBase = blockIdx.y * BMT;
    const int colBase = blockIdx.x * BNT;

    const uint32_t aBase = smb;
    const uint32_t bBase = smb + STAGES * A_STAGE_B;

    // ldmatrix per-thread addresses (byte offsets within one stage)
    // lanes 0-7 -> matrix0, 8-15 -> m1, 16-23 -> m2, 24-31 -> m3
    const int g  = lane >> 3;      // 0..3
    const int r8 = lane & 7;       // row within matrix
    uint32_t aoff[4], boff[4];
#pragma unroll
    for (int mt = 0; mt < 4; mt++)   // m0:(+0,k0) m1:(+8,k0) m2:(+0,k4) m3:(+8,k4)
        aoff[mt] = (uint32_t)(((wm * 64 + mt * 16 + (g & 1) * 8 + r8) * SA + (g >> 1) * 4) * 4);
#pragma unroll
    for (int p = 0; p < 4; p++)      // m0:(nt,k0) m1:(nt,k4) m2:(nt+1,k0) m3:(nt+1,k4)
        boff[p] = (uint32_t)(((wn * 64 + p * 16 + (g >> 1) * 8 + r8) * SA + (g & 1) * 4) * 4);

    // staging: 512 float4 per matrix / 128 threads = 4 cp16 each
    auto stage = [&](int kc, int st) {
        const int koff = kc * BKT;
        const uint32_t aso = aBase + st * A_STAGE_B;
        const uint32_t bso = bBase + st * BT_STAGE_B;
#pragma unroll
        for (int i = 0; i < 4; i++) {
            const int f = i * 128 + tid;
            const int row = f >> 2, k4 = f & 3;
            cp16(aso + row * (SA * 4) + k4 * 16, A  + (long long)(rowBase + row) * K + koff + k4 * 4);
            cp16(bso + row * (SA * 4) + k4 * 16, Bm + (long long)(colBase + row) * K + koff + k4 * 4);
        }
    };

    float acc[4][8][4];
#pragma unroll
    for (int i = 0; i < 4; i++)
#pragma unroll
        for (int j = 0; j < 8; j++)
#pragma unroll
            for (int r = 0; r < 4; r++) acc[i][j][r] = 0.0f;

    const int NC = K / BKT;
    stage(0, 0); CP_COMMIT();
    stage(1, 1); CP_COMMIT();

    int bufC = 0, bufS = 2;
    for (int c = 0; c < NC; c++) {
        CP_WAIT1();
        __syncthreads();
        if (c + 2 < NC) stage(c + 2, bufS);
        CP_COMMIT();

        const uint32_t aS = aBase + bufC * A_STAGE_B;
        const uint32_t bS = bBase + bufC * BT_STAGE_B;
#pragma unroll
        for (int ks = 0; ks < 2; ks++) {
            const uint32_t kk = (uint32_t)(ks * 8 * 4);   // 8 floats
            unsigned af[4][4], bf[8][2];
#pragma unroll
            for (int mt = 0; mt < 4; mt++)
                LDSM_X4(af[mt][0], af[mt][1], af[mt][2], af[mt][3], aS + aoff[mt] + kk);
#pragma unroll
            for (int p = 0; p < 4; p++)
                LDSM_X4(bf[2*p][0], bf[2*p][1], bf[2*p+1][0], bf[2*p+1][1], bS + boff[p] + kk);
#pragma unroll
            for (int mt = 0; mt < 4; mt++)
#pragma unroll
                for (int nt = 0; nt < 8; nt++)
                    mma_tf32(acc[mt][nt][0], acc[mt][nt][1], acc[mt][nt][2], acc[mt][nt][3],
                             af[mt][0], af[mt][1], af[mt][2], af[mt][3],
                             bf[nt][0], bf[nt][1]);
        }
        bufC = (bufC == STAGES - 1) ? 0 : bufC + 1;
        bufS = (bufS == STAGES - 1) ? 0 : bufS + 1;
    }

#pragma unroll
    for (int mt = 0; mt < 4; mt++) {
        const int row = rowBase + wm * 64 + mt * 16 + lq;
#pragma unroll
        for (int nt = 0; nt < 8; nt++) {
            const int col = colBase + wn * 64 + nt * 8 + 2 * lr;
            float v0 = acc[mt][nt][0], v1 = acc[mt][nt][1];
            float v2 = acc[mt][nt][2], v3 = acc[mt][nt][3];
            if (bias) { v0 += bias[col]; v1 += bias[col + 1]; v2 += bias[col]; v3 += bias[col + 1]; }
            v0 *= scale; v1 *= scale; v2 *= scale; v3 *= scale;
            if (roundOut) {
                v0 = __uint_as_float(f2tf(v0)); v1 = __uint_as_float(f2tf(v1));
                v2 = __uint_as_float(f2tf(v2)); v3 = __uint_as_float(f2tf(v3));
            }
            if (maskDiag) {
                if (row == col)     v0 = -3.402823466e38f;
                if (row == col + 1) v1 = -3.402823466e38f;
                if (row + 8 == col)     v2 = -3.402823466e38f;
                if (row + 8 == col + 1) v3 = -3.402823466e38f;
            }
            *(float2*)&C[(long long)row * N + col]       = make_float2(v0, v1);
            *(float2*)&C[(long long)(row + 8) * N + col] = make_float2(v2, v3);
        }
    }
}

// Per-batch transpose: out[b][o][t] = in[b][t][o]. 32x32 tiles.
__global__ __launch_bounds__(256) void transpose_bt(const float* __restrict__ in,
                                                    float* __restrict__ out)
{
    __shared__ float t[32][33];
    const int b = blockIdx.z;
    in  += (long long)b * L_ * H_;
    out += (long long)b * L_ * H_;
    const int tx = threadIdx.x, ty = threadIdx.y;
    const int x = blockIdx.x * 32 + tx;     // o (read col)
    const int y = blockIdx.y * 32 + ty;     // t (read row)
#pragma unroll
    for (int j = 0; j < 32; j += 8)
        t[ty + j][tx] = in[(long long)(y + j) * H_ + x];
    __syncthreads();
    const int xo = blockIdx.y * 32 + tx;    // t (write col)
    const int yo = blockIdx.x * 32 + ty;    // o (write row)
#pragma unroll
    for (int j = 0; j < 32; j += 8)
        out[(long long)(yo + j) * L_ + xo] = t[tx][ty + j];
}

// Round an f32 array to tf32 (rna), in -> out. Grid-stride float4.
__global__ __launch_bounds__(256) void round_tf32(const float* __restrict__ in,
                                                  float* __restrict__ out, long long n4)
{
    const long long i0 = (long long)blockIdx.x * blockDim.x + threadIdx.x;
    const long long stride = (long long)gridDim.x * blockDim.x;
    for (long long i = i0; i < n4; i += stride) {
        float4 v = ((const float4*)in)[i];
        ((float4*)out)[i] = make_float4(
            __uint_as_float(f2tf(v.x)), __uint_as_float(f2tf(v.y)),
            __uint_as_float(f2tf(v.z)), __uint_as_float(f2tf(v.w)));
    }
}

// In-place row softmax over 2048 columns; output rounded to tf32.
__global__ __launch_bounds__(256) void softmax_rows(float* __restrict__ S)
{
    __shared__ float red[256];
    float* row = S + (long long)blockIdx.x * L_;
    const int tid = threadIdx.x;

    float vals[8];
    float lmax = -3.402823466e38f;
#pragma unroll
    for (int i = 0; i < 8; i++) {
        vals[i] = row[tid + i * 256];
        lmax = fmaxf(lmax, vals[i]);
    }
    red[tid] = lmax;
    __syncthreads();
    for (int s = 128; s > 0; s >>= 1) {
        if (tid < s) red[tid] = fmaxf(red[tid], red[tid + s]);
        __syncthreads();
    }
    const float m = red[0];
    __syncthreads();

    float lsum = 0.0f;
#pragma unroll
    for (int i = 0; i < 8; i++) {
        vals[i] = __expf(vals[i] - m);
        lsum += vals[i];
    }
    red[tid] = lsum;
    __syncthreads();
    for (int s = 128; s > 0; s >>= 1) {
        if (tid < s) red[tid] += red[tid + s];
        __syncthreads();
    }
    const float inv = 1.0f / red[0];
#pragma unroll
    for (int i = 0; i < 8; i++)
        row[tid + i * 256] = __uint_as_float(f2tf(vals[i] * inv));
}

extern "C" void kernel_launch(void* const* d_in, const int* in_sizes, int n_in,
                              void* d_out, int out_size)
{
    const float* x  = (const float*)d_in[0];
    const float* Wq = (const float*)d_in[1];
    const float* bq = (const float*)d_in[2];
    const float* Wk = (const float*)d_in[3];
    const float* bk = (const float*)d_in[4];
    const float* Wv = (const float*)d_in[5];
    const float* bv = (const float*)d_in[6];
    float* out = (float*)d_out;

    float *q, *k, *v, *s, *xr, *wr;
    cudaGetSymbolAddress((void**)&q,  g_q);
    cudaGetSymbolAddress((void**)&k,  g_k);
    cudaGetSymbolAddress((void**)&v,  g_v);
    cudaGetSymbolAddress((void**)&s,  g_s);
    cudaGetSymbolAddress((void**)&xr, g_x);
    cudaGetSymbolAddress((void**)&wr, g_w);

    cudaFuncSetAttribute(gemm_nt_cp, cudaFuncAttributeMaxDynamicSharedMemorySize, NT_SMEM);

    const long long sQK = (long long)L_ * H_;
    const long long sSS = (long long)L_ * L_;

    // Pre-round x and W to tf32 so cp.async-staged mma inputs are exact.
    round_tf32<<<1024, 256>>>(x, xr, (long long)B_ * L_ * H_ / 4);
    round_tf32<<<256, 256>>>(Wq, wr,                       (long long)H_ * H_ / 4);
    round_tf32<<<256, 256>>>(Wk, wr + (size_t)H_ * H_,     (long long)H_ * H_ / 4);
    round_tf32<<<256, 256>>>(Wv, wr + (size_t)2 * H_ * H_, (long long)H_ * H_ / 4);

    const dim3 blk(128);

    // QKV projections (q folded with 1/H scale); outputs rounded to tf32
    dim3 gQKV(H_ / BNT, (B_ * L_) / BMT, 1);
    gemm_nt_cp<<<gQKV, blk, NT_SMEM>>>(xr, wr,                   bq, q, B_ * L_, H_, H_, 1.0f / (float)H_, 0, 1, 0, 0, 0);
    gemm_nt_cp<<<gQKV, blk, NT_SMEM>>>(xr, wr + (size_t)H_ * H_, bk, k, B_ * L_, H_, H_, 1.0f, 0, 1, 0, 0, 0);
    gemm_nt_cp<<<gQKV, blk, NT_SMEM>>>(xr, wr + (size_t)2*H_*H_, bv, v, B_ * L_, H_, H_, 1.0f, 0, 1, 0, 0, 0);

    // V^T into the (now dead) xr buffer: vt[b][o][t] = v[b][t][o]
    float* vt = xr;
    dim3 gT(H_ / 32, L_ / 32, B_);
    transpose_bt<<<gT, dim3(32, 8)>>>(v, vt);

    // Scores: S[b] = q[b]*k[b]^T, diagonal masked (f32; softmax rounds)
    dim3 gS(L_ / BNT, L_ / BMT, B_);
    gemm_nt_cp<<<gS, blk, NT_SMEM>>>(q, k, nullptr, s, L_, L_, H_, 1.0f, 1, 0, sQK, sQK, sSS);

    softmax_rows<<<B_ * L_, 256>>>(s);

    // Output: out[b] = S[b] * (V^T[b])^T  — NT with B = V^T (K=L contiguous)
    dim3 gO(H_ / BNT, L_ / BMT, B_);
    gemm_nt_cp<<<gO, blk, NT_SMEM>>>(s, vt, nullptr, out, L_, H_, L_, 1.0f, 0, 0, sSS, sQK, sQK);
}

// round 7
// speedup vs baseline: 2.4217x; 1.9161x over previous
#include <cuda_runtime.h>
#include <cuda_fp16.h>
#include <cstdint>

#define B_ 8
#define L_ 2048
#define H_ 1024

// Scratch: __device__ globals (no cudaMalloc allowed anywhere)
__device__ __half g_xh[(size_t)B_ * L_ * H_];   // 32 MB  fp16 x
__device__ __half g_wh[(size_t)3 * H_ * H_];    // 6 MB   fp16 Wq|Wk|Wv
__device__ __half g_qh[(size_t)B_ * L_ * H_];   // 32 MB
__device__ __half g_kh[(size_t)B_ * L_ * H_];   // 32 MB
__device__ __half g_vh[(size_t)B_ * L_ * H_];   // 32 MB
__device__ __half g_vth[(size_t)B_ * L_ * H_];  // 32 MB  V^T [b][o][t]
__device__ __half g_p[(size_t)B_ * L_ * L_];    // 64 MB  softmax probs
__device__ float  g_s[(size_t)B_ * L_ * L_];    // 128 MB scores (f32)

// ---- fp16 mma.sync m16n8k16 GEMM: block 128x128, 4 warps (2x2) of 64x64,
// ---- BK=32, 3-stage cp.async, ldmatrix.x4 fragments.
#define BMT 128
#define BNT 128
#define BKT 32
#define STAGES 3
#define SAH 40    // smem row stride in halves (80B): conflict-free ldmatrix

#define A_STAGE_B (BMT * SAH * 2)                // 10240 bytes
#define NT_SMEM (STAGES * 2 * A_STAGE_B)         // 61440

__device__ __forceinline__ uint32_t smem_u32(const void* p) {
    uint32_t a;
    asm("{ .reg .u64 t; cvta.to.shared.u64 t, %1; cvt.u32.u64 %0, t; }" : "=r"(a) : "l"(p));
    return a;
}
__device__ __forceinline__ void cp16(uint32_t dst, const void* src) {
    asm volatile("cp.async.cg.shared.global [%0], [%1], 16;" :: "r"(dst), "l"(src));
}
#define CP_COMMIT() asm volatile("cp.async.commit_group;" ::: "memory")
#define CP_WAIT1()  asm volatile("cp.async.wait_group 1;" ::: "memory")

#define LDSM_X4(d0, d1, d2, d3, addr)                                        \
    asm volatile("ldmatrix.sync.aligned.m8n8.x4.shared.b16 {%0,%1,%2,%3}, [%4];" \
        : "=r"(d0), "=r"(d1), "=r"(d2), "=r"(d3) : "r"(addr))

__device__ __forceinline__ void mma_f16(float& d0, float& d1, float& d2, float& d3,
                                        unsigned a0, unsigned a1, unsigned a2, unsigned a3,
                                        unsigned b0, unsigned b1) {
    asm volatile(
        "mma.sync.aligned.m16n8k16.row.col.f32.f16.f16.f32 "
        "{%0,%1,%2,%3}, {%4,%5,%6,%7}, {%8,%9}, {%0,%1,%2,%3};\n"
        : "+f"(d0), "+f"(d1), "+f"(d2), "+f"(d3)
        : "r"(a0), "r"(a1), "r"(a2), "r"(a3), "r"(b0), "r"(b1));
}

// C[M,N] = scale*(A[M,K]*B[N,K]^T + bias); A,B half K-contiguous (NT).
// Output: Ch != nullptr -> half (rne); else Cf f32 (with optional diag mask).
__global__ __launch_bounds__(128, 2) void gemm_nt_h(
    const __half* __restrict__ A, const __half* __restrict__ Bm,
    const float* __restrict__ bias, __half* __restrict__ Ch, float* __restrict__ Cf,
    int M, int N, int K, float scale, int maskDiag,
    long long sA, long long sB, long long sC)
{
    extern __shared__ char sm[];
    const uint32_t smb = smem_u32(sm);

    A  += (long long)blockIdx.z * sA;
    Bm += (long long)blockIdx.z * sB;
    if (Ch) Ch += (long long)blockIdx.z * sC;
    if (Cf) Cf += (long long)blockIdx.z * sC;

    const int tid  = threadIdx.x;
    const int warp = tid >> 5;
    const int lane = tid & 31;
    const int lq = lane >> 2, lr = lane & 3;
    const int wm = warp >> 1, wn = warp & 1;        // 2x2 warps, 64x64 each
    const int rowBase = blockIdx.y * BMT;
    const int colBase = blockIdx.x * BNT;

    const uint32_t aBase = smb;
    const uint32_t bBase = smb + STAGES * A_STAGE_B;

    // ldmatrix per-thread base offsets (bytes within one stage)
    const int g  = lane >> 3;      // 0..3
    const int r8 = lane & 7;
    uint32_t aoff[4], boff[4];
#pragma unroll
    for (int mt = 0; mt < 4; mt++)   // A x4: m0=(r,k0) m1=(r+8,k0) m2=(r,k8) m3=(r+8,k8)
        aoff[mt] = (uint32_t)((wm * 64 + mt * 16 + (g & 1) * 8 + r8) * (SAH * 2) + (g >> 1) * 16);
#pragma unroll
    for (int p = 0; p < 4; p++)      // B x4: m0=(n,k0) m1=(n,k8) m2=(n+8,k0) m3=(n+8,k8)
        boff[p] = (uint32_t)((wn * 64 + p * 16 + (g >> 1) * 8 + r8) * (SAH * 2) + (g & 1) * 16);

    // staging: 128 rows x 32 halves = 64B/row = 4 cp16; 512 cp16 per matrix
    auto stage = [&](int kc, int st) {
        const int koff = kc * BKT;
        const uint32_t aso = aBase + st * A_STAGE_B;
        const uint32_t bso = bBase + st * A_STAGE_B;
#pragma unroll
        for (int i = 0; i < 4; i++) {
            const int f = i * 128 + tid;
            const int row = f >> 2, k4 = f & 3;
            cp16(aso + row * (SAH * 2) + k4 * 16, A  + (long long)(rowBase + row) * K + koff + k4 * 8);
            cp16(bso + row * (SAH * 2) + k4 * 16, Bm + (long long)(colBase + row) * K + koff + k4 * 8);
        }
    };

    float acc[4][8][4];
#pragma unroll
    for (int i = 0; i < 4; i++)
#pragma unroll
        for (int j = 0; j < 8; j++)
#pragma unroll
            for (int r = 0; r < 4; r++) acc[i][j][r] = 0.0f;

    const int NC = K / BKT;
    stage(0, 0); CP_COMMIT();
    stage(1, 1); CP_COMMIT();

    int bufC = 0, bufS = 2;
    for (int c = 0; c < NC; c++) {
        CP_WAIT1();
        __syncthreads();
        if (c + 2 < NC) stage(c + 2, bufS);
        CP_COMMIT();

        const uint32_t aS = aBase + bufC * A_STAGE_B;
        const uint32_t bS = bBase + bufC * A_STAGE_B;
#pragma unroll
        for (int ks = 0; ks < 2; ks++) {            // two k16 steps per BK=32
            const uint32_t kk = (uint32_t)(ks * 32); // 16 halves = 32 bytes
            unsigned af[4][4], bf[8][2];
#pragma unroll
            for (int mt = 0; mt < 4; mt++)
                LDSM_X4(af[mt][0], af[mt][1], af[mt][2], af[mt][3], aS + aoff[mt] + kk);
#pragma unroll
            for (int p = 0; p < 4; p++)
                LDSM_X4(bf[2*p][0], bf[2*p][1], bf[2*p+1][0], bf[2*p+1][1], bS + boff[p] + kk);
#pragma unroll
            for (int mt = 0; mt < 4; mt++)
#pragma unroll
                for (int nt = 0; nt < 8; nt++)
                    mma_f16(acc[mt][nt][0], acc[mt][nt][1], acc[mt][nt][2], acc[mt][nt][3],
                            af[mt][0], af[mt][1], af[mt][2], af[mt][3],
                            bf[nt][0], bf[nt][1]);
        }
        bufC = (bufC == STAGES - 1) ? 0 : bufC + 1;
        bufS = (bufS == STAGES - 1) ? 0 : bufS + 1;
    }

#pragma unroll
    for (int mt = 0; mt < 4; mt++) {
        const int row = rowBase + wm * 64 + mt * 16 + lq;
#pragma unroll
        for (int nt = 0; nt < 8; nt++) {
            const int col = colBase + wn * 64 + nt * 8 + 2 * lr;
            float v0 = acc[mt][nt][0], v1 = acc[mt][nt][1];
            float v2 = acc[mt][nt][2], v3 = acc[mt][nt][3];
            if (bias) { v0 += bias[col]; v1 += bias[col + 1]; v2 += bias[col]; v3 += bias[col + 1]; }
            v0 *= scale; v1 *= scale; v2 *= scale; v3 *= scale;
            if (Ch) {
                *(__half2*)&Ch[(long long)row * N + col]       = __floats2half2_rn(v0, v1);
                *(__half2*)&Ch[(long long)(row + 8) * N + col] = __floats2half2_rn(v2, v3);
            } else {
                if (maskDiag) {
                    if (row == col)     v0 = -3.402823466e38f;
                    if (row == col + 1) v1 = -3.402823466e38f;
                    if (row + 8 == col)     v2 = -3.402823466e38f;
                    if (row + 8 == col + 1) v3 = -3.402823466e38f;
                }
                *(float2*)&Cf[(long long)row * N + col]       = make_float2(v0, v1);
                *(float2*)&Cf[(long long)(row + 8) * N + col] = make_float2(v2, v3);
            }
        }
    }
}

// Per-batch fp16 transpose: out[b][o][t] = in[b][t][o]. 32x32 tiles.
__global__ __launch_bounds__(256) void transpose_bt_h(const __half* __restrict__ in,
                                                      __half* __restrict__ out)
{
    __shared__ __half t[32][33];
    const int b = blockIdx.z;
    in  += (long long)b * L_ * H_;
    out += (long long)b * L_ * H_;
    const int tx = threadIdx.x, ty = threadIdx.y;
    const int x = blockIdx.x * 32 + tx;     // o
    const int y = blockIdx.y * 32 + ty;     // t
#pragma unroll
    for (int j = 0; j < 32; j += 8)
        t[ty + j][tx] = in[(long long)(y + j) * H_ + x];
    __syncthreads();
    const int xo = blockIdx.y * 32 + tx;    // t
    const int yo = blockIdx.x * 32 + ty;    // o
#pragma unroll
    for (int j = 0; j < 32; j += 8)
        out[(long long)(yo + j) * L_ + xo] = t[tx][ty + j];
}

// Round f32 -> fp16 (rne). Grid-stride, float4 in / half4 out.
__global__ __launch_bounds__(256) void round_f16(const float* __restrict__ in,
                                                 __half* __restrict__ out, long long n4)
{
    const long long i0 = (long long)blockIdx.x * blockDim.x + threadIdx.x;
    const long long stride = (long long)gridDim.x * blockDim.x;
    for (long long i = i0; i < n4; i += stride) {
        float4 v = ((const float4*)in)[i];
        __half2 h0 = __floats2half2_rn(v.x, v.y);
        __half2 h1 = __floats2half2_rn(v.z, v.w);
        ((uint2*)out)[i] = make_uint2(*(uint32_t*)&h0, *(uint32_t*)&h1);
    }
}

// Row softmax over 2048 f32 scores -> fp16 probs.
__global__ __launch_bounds__(256) void softmax_rows(const float* __restrict__ S,
                                                    __half* __restrict__ P)
{
    __shared__ float red[256];
    const float* row = S + (long long)blockIdx.x * L_;
    __half* prow = P + (long long)blockIdx.x * L_;
    const int tid = threadIdx.x;

    float vals[8];
    float lmax = -3.402823466e38f;
#pragma unroll
    for (int i = 0; i < 8; i++) {
        vals[i] = row[tid + i * 256];
        lmax = fmaxf(lmax, vals[i]);
    }
    red[tid] = lmax;
    __syncthreads();
    for (int s = 128; s > 0; s >>= 1) {
        if (tid < s) red[tid] = fmaxf(red[tid], red[tid + s]);
        __syncthreads();
    }
    const float m = red[0];
    __syncthreads();

    float lsum = 0.0f;
#pragma unroll
    for (int i = 0; i < 8; i++) {
        vals[i] = __expf(vals[i] - m);
        lsum += vals[i];
    }
    red[tid] = lsum;
    __syncthreads();
    for (int s = 128; s > 0; s >>= 1) {
        if (tid < s) red[tid] += red[tid + s];
        __syncthreads();
    }
    const float inv = 1.0f / red[0];
#pragma unroll
    for (int i = 0; i < 8; i++)
        prow[tid + i * 256] = __float2half_rn(vals[i] * inv);
}

extern "C" void kernel_launch(void* const* d_in, const int* in_sizes, int n_in,
                              void* d_out, int out_size)
{
    const float* x  = (const float*)d_in[0];
    const float* Wq = (const float*)d_in[1];
    const float* bq = (const float*)d_in[2];
    const float* Wk = (const float*)d_in[3];
    const float* bk = (const float*)d_in[4];
    const float* Wv = (const float*)d_in[5];
    const float* bv = (const float*)d_in[6];
    float* out = (float*)d_out;

    __half *xh, *wh, *qh, *kh, *vh, *vth, *p;
    float *s;
    cudaGetSymbolAddress((void**)&xh,  g_xh);
    cudaGetSymbolAddress((void**)&wh,  g_wh);
    cudaGetSymbolAddress((void**)&qh,  g_qh);
    cudaGetSymbolAddress((void**)&kh,  g_kh);
    cudaGetSymbolAddress((void**)&vh,  g_vh);
    cudaGetSymbolAddress((void**)&vth, g_vth);
    cudaGetSymbolAddress((void**)&p,   g_p);
    cudaGetSymbolAddress((void**)&s,   g_s);

    cudaFuncSetAttribute(gemm_nt_h, cudaFuncAttributeMaxDynamicSharedMemorySize, NT_SMEM);

    const long long sQK = (long long)L_ * H_;
    const long long sSS = (long long)L_ * L_;

    // Round inputs to fp16 so all mma operands are exactly representable.
    round_f16<<<1024, 256>>>(x, xh, (long long)B_ * L_ * H_ / 4);
    round_f16<<<256, 256>>>(Wq, wh,                       (long long)H_ * H_ / 4);
    round_f16<<<256, 256>>>(Wk, wh + (size_t)H_ * H_,     (long long)H_ * H_ / 4);
    round_f16<<<256, 256>>>(Wv, wh + (size_t)2 * H_ * H_, (long long)H_ * H_ / 4);

    const dim3 blk(128);

    // QKV projections -> fp16 (q folded with 1/H scale)
    dim3 gQKV(H_ / BNT, (B_ * L_) / BMT, 1);
    gemm_nt_h<<<gQKV, blk, NT_SMEM>>>(xh, wh,                   bq, qh, nullptr, B_ * L_, H_, H_, 1.0f / (float)H_, 0, 0, 0, 0);
    gemm_nt_h<<<gQKV, blk, NT_SMEM>>>(xh, wh + (size_t)H_ * H_, bk, kh, nullptr, B_ * L_, H_, H_, 1.0f, 0, 0, 0, 0);
    gemm_nt_h<<<gQKV, blk, NT_SMEM>>>(xh, wh + (size_t)2*H_*H_, bv, vh, nullptr, B_ * L_, H_, H_, 1.0f, 0, 0, 0, 0);

    // V^T (fp16): vt[b][o][t] = v[b][t][o]
    dim3 gT(H_ / 32, L_ / 32, B_);
    transpose_bt_h<<<gT, dim3(32, 8)>>>(vh, vth);

    // Scores: S[b] = q[b]*k[b]^T (f32 out, diag masked)
    dim3 gS(L_ / BNT, L_ / BMT, B_);
    gemm_nt_h<<<gS, blk, NT_SMEM>>>(qh, kh, nullptr, nullptr, s, L_, L_, H_, 1.0f, 1, sQK, sQK, sSS);

    // Softmax f32 scores -> fp16 probs
    softmax_rows<<<B_ * L_, 256>>>(s, p);

    // Output: out[b] = P[b] * (V^T[b])^T  (NT, f32 out)
    dim3 gO(H_ / BNT, L_ / BMT, B_);
    gemm_nt_h<<<gO, blk, NT_SMEM>>>(p, vth, nullptr, nullptr, out, L_, H_, L_, 1.0f, 0, sSS, sQK, sQK);
}

// round 8
// speedup vs baseline: 2.8013x; 1.1568x over previous
#include <cuda_runtime.h>
#include <cuda_fp16.h>
#include <cstdint>

#define B_ 8
#define L_ 2048
#define H_ 1024

// Scratch: __device__ globals (no cudaMalloc allowed anywhere)
__device__ __half g_xh[(size_t)B_ * L_ * H_];        // 32 MB  fp16 x
__device__ __half g_wh[(size_t)3 * H_ * H_];         // 6 MB   fp16 Wq|Wk|Wv (row-concat)
__device__ float  g_bias[3 * H_];                    // packed bq|bk|bv
__device__ __half g_qkv[(size_t)B_ * L_ * 3 * H_];   // 96 MB  fused q|k|v per row
__device__ __half g_p[(size_t)B_ * L_ * L_];         // 64 MB  softmax probs
__device__ float  g_s[(size_t)B_ * L_ * L_];         // 128 MB scores (f32)

// ---- fp16 mma.sync m16n8k16 GEMM: block 128x128, 4 warps (2x2) of 64x64,
// ---- BK=32, 4-stage cp.async, ldmatrix.x4 (+ .trans for N-major B).
#define BMT 128
#define BNT 128
#define BKT 32
#define STAGES 4
#define SAH 40    // K-major smem row stride (halves): conflict-free ldmatrix
#define SBH 136   // N-major smem row stride (halves): conflict-free trans ldmatrix

#define A_STAGE_B (BMT * SAH * 2)                // 10240 bytes (also used for B)
#define NT_SMEM (STAGES * 2 * A_STAGE_B)         // 81920

__device__ __forceinline__ uint32_t smem_u32(const void* p) {
    uint32_t a;
    asm("{ .reg .u64 t; cvta.to.shared.u64 t, %1; cvt.u32.u64 %0, t; }" : "=r"(a) : "l"(p));
    return a;
}
__device__ __forceinline__ void cp16(uint32_t dst, const void* src) {
    asm volatile("cp.async.cg.shared.global [%0], [%1], 16;" :: "r"(dst), "l"(src));
}
#define CP_COMMIT() asm volatile("cp.async.commit_group;" ::: "memory")
#define CP_WAIT2()  asm volatile("cp.async.wait_group 2;" ::: "memory")

#define LDSM_X4(d0, d1, d2, d3, addr)                                            \
    asm volatile("ldmatrix.sync.aligned.m8n8.x4.shared.b16 {%0,%1,%2,%3}, [%4];" \
        : "=r"(d0), "=r"(d1), "=r"(d2), "=r"(d3) : "r"(addr))
#define LDSM_X4_T(d0, d1, d2, d3, addr)                                          \
    asm volatile("ldmatrix.sync.aligned.m8n8.x4.trans.shared.b16 {%0,%1,%2,%3}, [%4];" \
        : "=r"(d0), "=r"(d1), "=r"(d2), "=r"(d3) : "r"(addr))

__device__ __forceinline__ void mma_f16(float& d0, float& d1, float& d2, float& d3,
                                        unsigned a0, unsigned a1, unsigned a2, unsigned a3,
                                        unsigned b0, unsigned b1) {
    asm volatile(
        "mma.sync.aligned.m16n8k16.row.col.f32.f16.f16.f32 "
        "{%0,%1,%2,%3}, {%4,%5,%6,%7}, {%8,%9}, {%0,%1,%2,%3};\n"
        : "+f"(d0), "+f"(d1), "+f"(d2), "+f"(d3)
        : "r"(a0), "r"(a1), "r"(a2), "r"(a3), "r"(b0), "r"(b1));
}

// C[M,N] = sc(col)*(A[M,K]*op(B) + bias).
//  bTrans=0: B is [N][K] K-contiguous (ldb = row stride).  (NT)
//  bTrans=1: B is [K][N] N-contiguous (ldb = row stride) — V in natural layout.
//  sc(col) = (col < splitCol) ? scale0 : scale1.
//  Ch != nullptr -> half out (rne); else Cf f32 (+ optional diagonal mask).
__global__ __launch_bounds__(128, 2) void gemm_h(
    const __half* __restrict__ A, const __half* __restrict__ Bm,
    const float* __restrict__ bias, __half* __restrict__ Ch, float* __restrict__ Cf,
    int M, int N, int K, int lda, int ldb, int ldc,
    float scale0, int splitCol, float scale1, int maskDiag, int bTrans,
    long long sA, long long sB, long long sC)
{
    extern __shared__ char sm[];
    const uint32_t smb = smem_u32(sm);

    A  += (long long)blockIdx.z * sA;
    Bm += (long long)blockIdx.z * sB;
    if (Ch) Ch += (long long)blockIdx.z * sC;
    if (Cf) Cf += (long long)blockIdx.z * sC;

    const int tid  = threadIdx.x;
    const int warp = tid >> 5;
    const int lane = tid & 31;
    const int lq = lane >> 2, lr = lane & 3;
    const int wm = warp >> 1, wn = warp & 1;        // 2x2 warps, 64x64 each
    const int rowBase = blockIdx.y * BMT;
    const int colBase = blockIdx.x * BNT;

    const uint32_t aBase = smb;
    const uint32_t bBase = smb + STAGES * A_STAGE_B;

    // ldmatrix per-thread base offsets (bytes within one stage)
    const int g  = lane >> 3;      // 0..3
    const int r8 = lane & 7;
    uint32_t aoff[4], boff[4];
#pragma unroll
    for (int mt = 0; mt < 4; mt++)   // A x4: m0=(r,k0) m1=(r+8,k0) m2=(r,k8) m3=(r+8,k8)
        aoff[mt] = (uint32_t)((wm * 64 + mt * 16 + (g & 1) * 8 + r8) * (SAH * 2) + (g >> 1) * 16);
    if (!bTrans) {
#pragma unroll
        for (int p = 0; p < 4; p++)  // B x4: m0=(n,k0) m1=(n,k8) m2=(n+8,k0) m3=(n+8,k8)
            boff[p] = (uint32_t)((wn * 64 + p * 16 + (g >> 1) * 8 + r8) * (SAH * 2) + (g & 1) * 16);
    } else {
#pragma unroll
        for (int p = 0; p < 4; p++)  // trans: m0=(k0-7,n) m1=(k8-15,n) m2=(k0-7,n+8) m3=(k8-15,n+8)
            boff[p] = (uint32_t)(((g & 1) * 8 + r8) * (SBH * 2) + (wn * 64 + p * 16 + (g >> 1) * 8) * 2);
    }

    auto stage = [&](int kc, int st) {
        const int koff = kc * BKT;
        const uint32_t aso = aBase + st * A_STAGE_B;
        const uint32_t bso = bBase + st * A_STAGE_B;
#pragma unroll
        for (int i = 0; i < 4; i++) {
            const int f = i * 128 + tid;
            const int arow = f >> 2, ak4 = f & 3;   // 128 rows x 4 cp16
            cp16(aso + arow * (SAH * 2) + ak4 * 16,
                 A + (long long)(rowBase + arow) * lda + koff + ak4 * 8);
            if (!bTrans) {
                cp16(bso + arow * (SAH * 2) + ak4 * 16,
                     Bm + (long long)(colBase + arow) * ldb + koff + ak4 * 8);
            } else {
                const int brow = f >> 4, bc4 = f & 15;  // 32 k-rows x 16 cp16
                cp16(bso + brow * (SBH * 2) + bc4 * 16,
                     Bm + (long long)(koff + brow) * ldb + colBase + bc4 * 8);
            }
        }
    };

    float acc[4][8][4];
#pragma unroll
    for (int i = 0; i < 4; i++)
#pragma unroll
        for (int j = 0; j < 8; j++)
#pragma unroll
            for (int r = 0; r < 4; r++) acc[i][j][r] = 0.0f;

    const int NC = K / BKT;
    stage(0, 0); CP_COMMIT();
    stage(1, 1); CP_COMMIT();
    stage(2, 2); CP_COMMIT();

    int bufC = 0, bufS = 3;
    for (int c = 0; c < NC; c++) {
        CP_WAIT2();
        __syncthreads();
        if (c + 3 < NC) stage(c + 3, bufS);
        CP_COMMIT();

        const uint32_t aS = aBase + bufC * A_STAGE_B;
        const uint32_t bS = bBase + bufC * A_STAGE_B;
#pragma unroll
        for (int ks = 0; ks < 2; ks++) {            // two k16 steps per BK=32
            unsigned af[4][4], bf[8][2];
#pragma unroll
            for (int mt = 0; mt < 4; mt++)
                LDSM_X4(af[mt][0], af[mt][1], af[mt][2], af[mt][3],
                        aS + aoff[mt] + (uint32_t)(ks * 32));
            if (!bTrans) {
#pragma unroll
                for (int p = 0; p < 4; p++)
                    LDSM_X4(bf[2*p][0], bf[2*p][1], bf[2*p+1][0], bf[2*p+1][1],
                            bS + boff[p] + (uint32_t)(ks * 32));
            } else {
#pragma unroll
                for (int p = 0; p < 4; p++)
                    LDSM_X4_T(bf[2*p][0], bf[2*p][1], bf[2*p+1][0], bf[2*p+1][1],
                              bS + boff[p] + (uint32_t)(ks * 16 * (SBH * 2)));
            }
#pragma unroll
            for (int mt = 0; mt < 4; mt++)
#pragma unroll
                for (int nt = 0; nt < 8; nt++)
                    mma_f16(acc[mt][nt][0], acc[mt][nt][1], acc[mt][nt][2], acc[mt][nt][3],
                            af[mt][0], af[mt][1], af[mt][2], af[mt][3],
                            bf[nt][0], bf[nt][1]);
        }
        bufC = (bufC == STAGES - 1) ? 0 : bufC + 1;
        bufS = (bufS == STAGES - 1) ? 0 : bufS + 1;
    }

#pragma unroll
    for (int mt = 0; mt < 4; mt++) {
        const int row = rowBase + wm * 64 + mt * 16 + lq;
#pragma unroll
        for (int nt = 0; nt < 8; nt++) {
            const int col = colBase + wn * 64 + nt * 8 + 2 * lr;
            float v0 = acc[mt][nt][0], v1 = acc[mt][nt][1];
            float v2 = acc[mt][nt][2], v3 = acc[mt][nt][3];
            if (bias) { v0 += bias[col]; v1 += bias[col + 1]; v2 += bias[col]; v3 += bias[col + 1]; }
            const float s0 = (col     < splitCol) ? scale0 : scale1;
            const float s1 = (col + 1 < splitCol) ? scale0 : scale1;
            v0 *= s0; v1 *= s1; v2 *= s0; v3 *= s1;
            if (Ch) {
                *(__half2*)&Ch[(long long)row * ldc + col]       = __floats2half2_rn(v0, v1);
                *(__half2*)&Ch[(long long)(row + 8) * ldc + col] = __floats2half2_rn(v2, v3);
            } else {
                if (maskDiag) {
                    if (row == col)     v0 = -3.402823466e38f;
                    if (row == col + 1) v1 = -3.402823466e38f;
                    if (row + 8 == col)     v2 = -3.402823466e38f;
                    if (row + 8 == col + 1) v3 = -3.402823466e38f;
                }
                *(float2*)&Cf[(long long)row * ldc + col]       = make_float2(v0, v1);
                *(float2*)&Cf[(long long)(row + 8) * ldc + col] = make_float2(v2, v3);
            }
        }
    }
}

// Round f32 -> fp16 (rne). Grid-stride, float4 in / 4x half out.
__global__ __launch_bounds__(256) void round_f16(const float* __restrict__ in,
                                                 __half* __restrict__ out, long long n4)
{
    const long long i0 = (long long)blockIdx.x * blockDim.x + threadIdx.x;
    const long long stride = (long long)gridDim.x * blockDim.x;
    for (long long i = i0; i < n4; i += stride) {
        float4 v = ((const float4*)in)[i];
        __half2 h0 = __floats2half2_rn(v.x, v.y);
        __half2 h1 = __floats2half2_rn(v.z, v.w);
        ((uint2*)out)[i] = make_uint2(*(uint32_t*)&h0, *(uint32_t*)&h1);
    }
}

// Pack bq|bk|bv into one 3H array.
__global__ void pack_bias(const float* __restrict__ bq, const float* __restrict__ bk,
                          const float* __restrict__ bv, float* __restrict__ out)
{
    const int i = blockIdx.x * blockDim.x + threadIdx.x;
    if (i < H_)            out[i] = bq[i];
    else if (i < 2 * H_)   out[i] = bk[i - H_];
    else if (i < 3 * H_)   out[i] = bv[i - 2 * H_];
}

// Row softmax over 2048 f32 scores -> fp16 probs.
__global__ __launch_bounds__(256) void softmax_rows(const float* __restrict__ S,
                                                    __half* __restrict__ P)
{
    __shared__ float red[256];
    const float* row = S + (long long)blockIdx.x * L_;
    __half* prow = P + (long long)blockIdx.x * L_;
    const int tid = threadIdx.x;

    float vals[8];
    float lmax = -3.402823466e38f;
#pragma unroll
    for (int i = 0; i < 8; i++) {
        vals[i] = row[tid + i * 256];
        lmax = fmaxf(lmax, vals[i]);
    }
    red[tid] = lmax;
    __syncthreads();
    for (int s = 128; s > 0; s >>= 1) {
        if (tid < s) red[tid] = fmaxf(red[tid], red[tid + s]);
        __syncthreads();
    }
    const float m = red[0];
    __syncthreads();

    float lsum = 0.0f;
#pragma unroll
    for (int i = 0; i < 8; i++) {
        vals[i] = __expf(vals[i] - m);
        lsum += vals[i];
    }
    red[tid] = lsum;
    __syncthreads();
    for (int s = 128; s > 0; s >>= 1) {
        if (tid < s) red[tid] += red[tid + s];
        __syncthreads();
    }
    const float inv = 1.0f / red[0];
#pragma unroll
    for (int i = 0; i < 8; i++)
        prow[tid + i * 256] = __float2half_rn(vals[i] * inv);
}

extern "C" void kernel_launch(void* const* d_in, const int* in_sizes, int n_in,
                              void* d_out, int out_size)
{
    const float* x  = (const float*)d_in[0];
    const float* Wq = (const float*)d_in[1];
    const float* bq = (const float*)d_in[2];
    const float* Wk = (const float*)d_in[3];
    const float* bk = (const float*)d_in[4];
    const float* Wv = (const float*)d_in[5];
    const float* bv = (const float*)d_in[6];
    float* out = (float*)d_out;

    __half *xh, *wh, *qkv, *p;
    float *s, *bias;
    cudaGetSymbolAddress((void**)&xh,   g_xh);
    cudaGetSymbolAddress((void**)&wh,   g_wh);
    cudaGetSymbolAddress((void**)&qkv,  g_qkv);
    cudaGetSymbolAddress((void**)&p,    g_p);
    cudaGetSymbolAddress((void**)&s,    g_s);
    cudaGetSymbolAddress((void**)&bias, g_bias);

    cudaFuncSetAttribute(gemm_h, cudaFuncAttributeMaxDynamicSharedMemorySize, NT_SMEM);

    const long long sQKV = (long long)L_ * 3 * H_;
    const long long sSS  = (long long)L_ * L_;
    const long long sO   = (long long)L_ * H_;

    // Round inputs to fp16 (exact mma operands); pack bias.
    round_f16<<<1024, 256>>>(x, xh, (long long)B_ * L_ * H_ / 4);
    round_f16<<<256, 256>>>(Wq, wh,                       (long long)H_ * H_ / 4);
    round_f16<<<256, 256>>>(Wk, wh + (size_t)H_ * H_,     (long long)H_ * H_ / 4);
    round_f16<<<256, 256>>>(Wv, wh + (size_t)2 * H_ * H_, (long long)H_ * H_ / 4);
    pack_bias<<<12, 256>>>(bq, bk, bv, bias);

    const dim3 blk(128);

    // Fused QKV projection: qkv[r][0:1024]=q (scaled 1/H), [1024:2048]=k, [2048:3072]=v
    dim3 gQKV(3 * H_ / BNT, (B_ * L_) / BMT, 1);
    gemm_h<<<gQKV, blk, NT_SMEM>>>(xh, wh, bias, qkv, nullptr,
                                   B_ * L_, 3 * H_, H_, H_, H_, 3 * H_,
                                   1.0f / (float)H_, H_, 1.0f, 0, 0, 0, 0, 0);

    // Scores: S[b] = q[b]*k[b]^T (f32, diag masked). q,k are slices of qkv.
    dim3 gS(L_ / BNT, L_ / BMT, B_);
    gemm_h<<<gS, blk, NT_SMEM>>>(qkv, qkv + H_, nullptr, nullptr, s,
                                 L_, L_, H_, 3 * H_, 3 * H_, L_,
                                 1.0f, 0, 1.0f, 1, 0, sQKV, sQKV, sSS);

    // Softmax f32 scores -> fp16 probs
    softmax_rows<<<B_ * L_, 256>>>(s, p);

    // Output: out[b] = P[b] * V[b]  (V N-major in qkv, trans-ldmatrix path)
    dim3 gO(H_ / BNT, L_ / BMT, B_);
    gemm_h<<<gO, blk, NT_SMEM>>>(p, qkv + 2 * H_, nullptr, nullptr, out,
                                 L_, H_, L_, L_, 3 * H_, H_,
                                 1.0f, 0, 1.0f, 0, 1, sSS, sQKV, sO);
}